// round 2
// baseline (speedup 1.0000x reference)
#include <cuda_runtime.h>
#include <cooperative_groups.h>

namespace cg = cooperative_groups;

#define T_STEPS 512
#define BATCH   256
#define IN0     128
#define HID     256
#define G3      768   // 3*HID

// ---------------- scratch (static device arrays; allocation-free) ------------
__device__ float g_gi[(size_t)T_STEPS * BATCH * G3];   // 402 MB, reused by both layers
__device__ float g_h1[(size_t)T_STEPS * BATCH * HID];  // 134 MB, layer-0 outputs
__device__ float g_h2[BATCH * HID];                    // final hidden state

// =============================================================================
// SGEMM with bias:  C[M,N] = A[M,K] @ Bw[N,K]^T + bias[N]
// BM=BN=128, BK=8, 256 threads, 8x8 per-thread tile, double-buffered smem.
// =============================================================================
__global__ __launch_bounds__(256) void sgemm_bias(
    const float* __restrict__ A, const float* __restrict__ Bw,
    const float* __restrict__ bias, float* __restrict__ C,
    int M, int N, int K)
{
    __shared__ float As[2][8][128];
    __shared__ float Bs[2][8][128];

    const int bx = blockIdx.x;   // N tile
    const int by = blockIdx.y;   // M tile
    const int t  = threadIdx.x;
    const int tx = t & 15;       // 0..15
    const int ty = t >> 4;       // 0..15

    const float* Ab = A  + (size_t)by * 128 * K;
    const float* Bb = Bw + (size_t)bx * 128 * K;

    const int lrow = t >> 1;         // 0..127
    const int lcol = (t & 1) * 4;    // 0 or 4

    float4 aReg = *(const float4*)(Ab + (size_t)lrow * K + lcol);
    float4 bReg = *(const float4*)(Bb + (size_t)lrow * K + lcol);
#pragma unroll
    for (int i = 0; i < 4; i++) {
        As[0][lcol + i][lrow] = ((const float*)&aReg)[i];
        Bs[0][lcol + i][lrow] = ((const float*)&bReg)[i];
    }
    __syncthreads();

    float acc[8][8];
#pragma unroll
    for (int i = 0; i < 8; i++)
#pragma unroll
        for (int j = 0; j < 8; j++) acc[i][j] = 0.0f;

    const int nk = K >> 3;
    for (int kt = 0; kt < nk; kt++) {
        const int cur = kt & 1;
        const int nxt = cur ^ 1;
        if (kt + 1 < nk) {
            aReg = *(const float4*)(Ab + (size_t)lrow * K + (kt + 1) * 8 + lcol);
            bReg = *(const float4*)(Bb + (size_t)lrow * K + (kt + 1) * 8 + lcol);
        }
#pragma unroll
        for (int k = 0; k < 8; k++) {
            float av[8], bv[8];
            *(float4*)(av)     = *(const float4*)&As[cur][k][ty * 8];
            *(float4*)(av + 4) = *(const float4*)&As[cur][k][ty * 8 + 4];
            *(float4*)(bv)     = *(const float4*)&Bs[cur][k][tx * 8];
            *(float4*)(bv + 4) = *(const float4*)&Bs[cur][k][tx * 8 + 4];
#pragma unroll
            for (int i = 0; i < 8; i++)
#pragma unroll
                for (int j = 0; j < 8; j++) acc[i][j] += av[i] * bv[j];
        }
        if (kt + 1 < nk) {
#pragma unroll
            for (int i = 0; i < 4; i++) {
                As[nxt][lcol + i][lrow] = ((const float*)&aReg)[i];
                Bs[nxt][lcol + i][lrow] = ((const float*)&bReg)[i];
            }
        }
        __syncthreads();
    }

    // epilogue with bias
    const int nbase = bx * 128 + tx * 8;
    float bv[8];
    *(float4*)(bv)     = *(const float4*)(bias + nbase);
    *(float4*)(bv + 4) = *(const float4*)(bias + nbase + 4);
#pragma unroll
    for (int i = 0; i < 8; i++) {
        const size_t m = (size_t)by * 128 + ty * 8 + i;
        float* cp = C + m * N + nbase;
        float4 c0, c1;
        c0.x = acc[i][0] + bv[0]; c0.y = acc[i][1] + bv[1];
        c0.z = acc[i][2] + bv[2]; c0.w = acc[i][3] + bv[3];
        c1.x = acc[i][4] + bv[4]; c1.y = acc[i][5] + bv[5];
        c1.z = acc[i][6] + bv[6]; c1.w = acc[i][7] + bv[7];
        *(float4*)(cp)     = c0;
        *(float4*)(cp + 4) = c1;
    }
}

// =============================================================================
// Persistent GRU recurrence. Cluster of 4 CTAs handles 8 batch rows.
// CTA rank r owns hidden columns [r*64, r*64+64), i.e. 192 W_hh rows in SMEM.
// h double-buffered in SMEM, broadcast to peers via DSMEM; 1 cluster.sync/step.
// 128 threads: thread t -> jj = t&63 (hidden col in slice), gb = t>>6.
// GEMM: each thread accumulates 3 gates x 4 batch rows (b = gb*4 .. gb*4+3).
// =============================================================================
#define WT_PITCH 193          // 192 rows padded -> conflict-free both directions
#define REC_SMEM_FLOATS (256 * WT_PITCH + 2 * 256 * 8 + 8 * 192 + 192)

__global__ void __cluster_dims__(4, 1, 1) __launch_bounds__(128, 1)
gru_rec(const float* __restrict__ Whh, const float* __restrict__ bhh_g,
        const float* __restrict__ gi, float* __restrict__ hout, int store_all)
{
    extern __shared__ float sm[];
    float* Wt   = sm;                          // [256][193]  (k-major, transposed)
    float* hbuf = Wt + 256 * WT_PITCH;         // [2][256][8]
    float* gh   = hbuf + 2 * 256 * 8;          // [8][192]
    float* bhh  = gh + 8 * 192;                // [192]

    cg::cluster_group cluster = cg::this_cluster();
    const int rank = cluster.block_rank();     // 0..3
    const int cid  = blockIdx.x >> 2;          // 0..31
    const int B0   = cid * 8;

    const int t  = threadIdx.x;
    const int jj = t & 63;
    const int gb = t >> 6;                     // 0 or 1

    // ---- load W_hh slice transposed: Wt[k][rr], rr = g*64 + jj ----
    for (int rr = 0; rr < 192; rr++) {
        const int grow = ((rr >> 6) << 8) + rank * 64 + (rr & 63);
        const float* wr = Whh + (size_t)grow * HID;
        for (int k = t; k < 256; k += 128) Wt[k * WT_PITCH + rr] = wr[k];
    }
    for (int rr = t; rr < 192; rr += 128)
        bhh[rr] = bhh_g[((rr >> 6) << 8) + rank * 64 + (rr & 63)];
    for (int i = t; i < 2 * 256 * 8; i += 128) hbuf[i] = 0.0f;
    __syncthreads();
    cluster.sync();   // peers will write into our hbuf; everyone must be zeroed

    const int kglob = rank * 64 + jj;          // global hidden index this thread owns

    for (int ts = 0; ts < T_STEPS; ts++) {
        const int p = ts & 1;
        const float* hrd = hbuf + p * 2048;

        // ---- prefetch gi for this step (12 values; used after the GEMM) ----
        float gv[12];
        {
            const float* gbase = gi + ((size_t)ts * BATCH + B0) * G3 + rank * 64 + jj;
#pragma unroll
            for (int i = 0; i < 4; i++) {
                const int b = gb + 2 * i;
                const float* gp = gbase + (size_t)b * G3;
                gv[i * 3 + 0] = __ldg(gp);
                gv[i * 3 + 1] = __ldg(gp + 256);
                gv[i * 3 + 2] = __ldg(gp + 512);
            }
        }

        // ---- GEMM: gh[b][g*64+jj] = sum_k h[k][b] * Wt[k][g*64+jj] ----
        float a0 = 0, a1 = 0, a2 = 0, a3 = 0, a4 = 0, a5 = 0;
        float a6 = 0, a7 = 0, a8 = 0, a9 = 0, a10 = 0, a11 = 0;
        const float* hp = hrd + gb * 4;
#pragma unroll 4
        for (int k = 0; k < 256; k++) {
            const float4 h4 = *(const float4*)(hp + (k << 3));
            const float w0 = Wt[k * WT_PITCH + jj];
            const float w1 = Wt[k * WT_PITCH + 64 + jj];
            const float w2 = Wt[k * WT_PITCH + 128 + jj];
            a0 += w0 * h4.x; a1 += w0 * h4.y; a2  += w0 * h4.z; a3  += w0 * h4.w;
            a4 += w1 * h4.x; a5 += w1 * h4.y; a6  += w1 * h4.z; a7  += w1 * h4.w;
            a8 += w2 * h4.x; a9 += w2 * h4.y; a10 += w2 * h4.z; a11 += w2 * h4.w;
        }
        {
            const int bb = gb * 4;
            gh[(bb + 0) * 192 +       jj] = a0;
            gh[(bb + 1) * 192 +       jj] = a1;
            gh[(bb + 2) * 192 +       jj] = a2;
            gh[(bb + 3) * 192 +       jj] = a3;
            gh[(bb + 0) * 192 +  64 + jj] = a4;
            gh[(bb + 1) * 192 +  64 + jj] = a5;
            gh[(bb + 2) * 192 +  64 + jj] = a6;
            gh[(bb + 3) * 192 +  64 + jj] = a7;
            gh[(bb + 0) * 192 + 128 + jj] = a8;
            gh[(bb + 1) * 192 + 128 + jj] = a9;
            gh[(bb + 2) * 192 + 128 + jj] = a10;
            gh[(bb + 3) * 192 + 128 + jj] = a11;
        }
        __syncthreads();

        // ---- gates + h update + DSMEM broadcast ----
        float* hwr = hbuf + (p ^ 1) * 2048;
        const float br = bhh[jj], bz = bhh[64 + jj], bn = bhh[128 + jj];
#pragma unroll
        for (int i = 0; i < 4; i++) {
            const int b = gb + 2 * i;
            const float hr = gh[b * 192 + jj]       + br;
            const float hz = gh[b * 192 + 64 + jj]  + bz;
            const float hn = gh[b * 192 + 128 + jj] + bn;
            const float r  = 1.0f / (1.0f + __expf(-(gv[i * 3 + 0] + hr)));
            const float z  = 1.0f / (1.0f + __expf(-(gv[i * 3 + 1] + hz)));
            const float n  = tanhf(gv[i * 3 + 2] + r * hn);
            const float hprev = hrd[(kglob << 3) + b];
            const float hnew  = (1.0f - z) * n + z * hprev;

            float* lp = hwr + (kglob << 3) + b;
#pragma unroll
            for (int q = 0; q < 4; q++) {
                float* dp = (float*)cluster.map_shared_rank(lp, q);
                *dp = hnew;
            }
            if (store_all) {
                hout[((size_t)ts * BATCH + B0 + b) * HID + kglob] = hnew;
            } else if (ts == T_STEPS - 1) {
                hout[(size_t)(B0 + b) * HID + kglob] = hnew;
            }
        }
        cluster.sync();
    }
}

// =============================================================================
// FC on the last hidden state: out[b][o] = dot(h2[b,:], W_fc[o,:]) + b_fc[o]
// =============================================================================
__global__ __launch_bounds__(256) void fc_kernel(
    const float* __restrict__ Wfc, const float* __restrict__ bfc,
    float* __restrict__ out)
{
    __shared__ float hs[256];
    const int b = blockIdx.x;
    const int o = threadIdx.x;
    hs[o] = g_h2[b * 256 + o];
    __syncthreads();
    const float* wr = Wfc + (size_t)o * 256;
    float acc = 0.0f;
#pragma unroll 8
    for (int k = 0; k < 256; k += 4) {
        const float4 w = *(const float4*)(wr + k);
        acc += hs[k] * w.x + hs[k + 1] * w.y + hs[k + 2] * w.z + hs[k + 3] * w.w;
    }
    out[b * 256 + o] = acc + bfc[o];
}

// =============================================================================
extern "C" void kernel_launch(void* const* d_in, const int* in_sizes, int n_in,
                              void* d_out, int out_size)
{
    const float* x     = (const float*)d_in[0];
    const float* W_ih0 = (const float*)d_in[1];
    const float* W_hh0 = (const float*)d_in[2];
    const float* b_ih0 = (const float*)d_in[3];
    const float* b_hh0 = (const float*)d_in[4];
    const float* W_ih1 = (const float*)d_in[5];
    const float* W_hh1 = (const float*)d_in[6];
    const float* b_ih1 = (const float*)d_in[7];
    const float* b_hh1 = (const float*)d_in[8];
    const float* W_fc  = (const float*)d_in[9];
    const float* b_fc  = (const float*)d_in[10];
    float* out = (float*)d_out;

    float *gi_p, *h1_p, *h2_p;
    cudaGetSymbolAddress((void**)&gi_p, g_gi);
    cudaGetSymbolAddress((void**)&h1_p, g_h1);
    cudaGetSymbolAddress((void**)&h2_p, g_h2);

    const size_t REC_SMEM = REC_SMEM_FLOATS * sizeof(float);  // 220,928 B
    cudaFuncSetAttribute(gru_rec, cudaFuncAttributeMaxDynamicSharedMemorySize,
                         (int)REC_SMEM);

    const int M = T_STEPS * BATCH;      // 131072
    dim3 gemm_grid(G3 / 128, M / 128);  // (6, 1024)

    // layer 0: gi0 = x @ W_ih0^T + b_ih0
    sgemm_bias<<<gemm_grid, 256>>>(x, W_ih0, b_ih0, gi_p, M, G3, IN0);
    // layer 0 recurrence -> g_h1[T,B,H]
    gru_rec<<<128, 128, REC_SMEM>>>(W_hh0, b_hh0, gi_p, h1_p, 1);
    // layer 1: gi1 = h1 @ W_ih1^T + b_ih1  (reuse g_gi)
    sgemm_bias<<<gemm_grid, 256>>>(h1_p, W_ih1, b_ih1, gi_p, M, G3, HID);
    // layer 1 recurrence -> g_h2[B,H] (final step only)
    gru_rec<<<128, 128, REC_SMEM>>>(W_hh1, b_hh1, gi_p, h2_p, 0);
    // FC head
    fc_kernel<<<BATCH, 256>>>(W_fc, b_fc, out);
}

// round 4
// speedup vs baseline: 1.1030x; 1.1030x over previous
#include <cuda_runtime.h>
#include <cooperative_groups.h>
#include <cstdint>

namespace cg = cooperative_groups;

#define T_STEPS 512
#define BATCH   256
#define IN0     128
#define HID     256
#define G3      768   // 3*HID

// ---------------- scratch (static device arrays; allocation-free) ------------
__device__ float g_gi[(size_t)T_STEPS * BATCH * G3];   // reused by both layers
__device__ float g_h1[(size_t)T_STEPS * BATCH * HID];  // layer-0 outputs
__device__ float g_h2[BATCH * HID];                    // final hidden state

// ======================= helpers ========================
__device__ __forceinline__ float f2tf32(float x) {
    float r;
    asm("cvt.rna.tf32.f32 %0, %1;" : "=f"(r) : "f"(x));
    return r;
}

__device__ __forceinline__ void mma_tf32(float* d, const float* a, const float* b) {
    asm volatile(
        "mma.sync.aligned.m16n8k8.row.col.f32.tf32.tf32.f32 "
        "{%0,%1,%2,%3}, {%4,%5,%6,%7}, {%8,%9}, {%0,%1,%2,%3};"
        : "+f"(d[0]), "+f"(d[1]), "+f"(d[2]), "+f"(d[3])
        : "r"(__float_as_uint(a[0])), "r"(__float_as_uint(a[1])),
          "r"(__float_as_uint(a[2])), "r"(__float_as_uint(a[3])),
          "r"(__float_as_uint(b[0])), "r"(__float_as_uint(b[1])));
}

// =============================================================================
// HMMA tf32 GEMM:  C[M,N] = A[M,K] @ Bw[N,K]^T + bias[N]
// CTA 128x128, BK=16 double-buffered, 8 warps, warp tile 32(M)x64(N).
// SMEM k-major, pitch 136 (mod 32 == 8 -> conflict-free fragment loads).
// =============================================================================
#define PITCH 136

__global__ __launch_bounds__(256, 2) void gemm_tf32mma(
    const float* __restrict__ A, const float* __restrict__ Bw,
    const float* __restrict__ bias, float* __restrict__ C,
    int N, int K)
{
    __shared__ float As[2][16][PITCH];
    __shared__ float Bs[2][16][PITCH];

    const int t    = threadIdx.x;
    const int bx   = blockIdx.x;     // N tile
    const int by   = blockIdx.y;     // M tile
    const int lane = t & 31;
    const int w    = t >> 5;
    const int wm   = w & 3;          // 0..3 -> M offset 32*wm
    const int wn   = w >> 2;         // 0..1 -> N offset 64*wn
    const int gid  = lane >> 2;      // 0..7
    const int tig  = lane & 3;       // 0..3

    const float* Ab = A  + (size_t)(by * 128) * K;
    const float* Bb = Bw + (size_t)(bx * 128) * K;

    // global->smem mapping: thread handles row lm, float4 slots f0, f0+1 (k dim)
    const int lm = t & 127;
    const int f0 = (t >> 7) * 2;     // 0 or 2

    float acc[2][8][4];
#pragma unroll
    for (int i = 0; i < 2; i++)
#pragma unroll
        for (int j = 0; j < 8; j++)
#pragma unroll
            for (int q = 0; q < 4; q++) acc[i][j][q] = 0.0f;

    // ---- prologue: stage 0 ----
    float4 pa[2], pb[2];
#pragma unroll
    for (int r = 0; r < 2; r++) {
        pa[r] = *(const float4*)(Ab + (size_t)lm * K + (f0 + r) * 4);
        pb[r] = *(const float4*)(Bb + (size_t)lm * K + (f0 + r) * 4);
    }
#pragma unroll
    for (int r = 0; r < 2; r++) {
        const int kk = (f0 + r) * 4;
        As[0][kk + 0][lm] = f2tf32(pa[r].x);
        As[0][kk + 1][lm] = f2tf32(pa[r].y);
        As[0][kk + 2][lm] = f2tf32(pa[r].z);
        As[0][kk + 3][lm] = f2tf32(pa[r].w);
        Bs[0][kk + 0][lm] = f2tf32(pb[r].x);
        Bs[0][kk + 1][lm] = f2tf32(pb[r].y);
        Bs[0][kk + 2][lm] = f2tf32(pb[r].z);
        Bs[0][kk + 3][lm] = f2tf32(pb[r].w);
    }
    __syncthreads();

    const int nst = K >> 4;
    for (int s = 0; s < nst; s++) {
        const int cur = s & 1;
        const bool pf = (s + 1 < nst);
        if (pf) {
            const int kbase = (s + 1) * 16;
#pragma unroll
            for (int r = 0; r < 2; r++) {
                pa[r] = *(const float4*)(Ab + (size_t)lm * K + kbase + (f0 + r) * 4);
                pb[r] = *(const float4*)(Bb + (size_t)lm * K + kbase + (f0 + r) * 4);
            }
        }
#pragma unroll
        for (int kk = 0; kk < 16; kk += 8) {
            float a[2][4], b[8][2];
#pragma unroll
            for (int i = 0; i < 2; i++) {
                const int m = wm * 32 + i * 16 + gid;
                a[i][0] = As[cur][kk + tig][m];
                a[i][1] = As[cur][kk + tig][m + 8];
                a[i][2] = As[cur][kk + tig + 4][m];
                a[i][3] = As[cur][kk + tig + 4][m + 8];
            }
#pragma unroll
            for (int j = 0; j < 8; j++) {
                const int n = wn * 64 + j * 8 + gid;
                b[j][0] = Bs[cur][kk + tig][n];
                b[j][1] = Bs[cur][kk + tig + 4][n];
            }
#pragma unroll
            for (int i = 0; i < 2; i++)
#pragma unroll
                for (int j = 0; j < 8; j++)
                    mma_tf32(acc[i][j], a[i], b[j]);
        }
        if (pf) {
            const int nxt = cur ^ 1;
#pragma unroll
            for (int r = 0; r < 2; r++) {
                const int kk = (f0 + r) * 4;
                As[nxt][kk + 0][lm] = f2tf32(pa[r].x);
                As[nxt][kk + 1][lm] = f2tf32(pa[r].y);
                As[nxt][kk + 2][lm] = f2tf32(pa[r].z);
                As[nxt][kk + 3][lm] = f2tf32(pa[r].w);
                Bs[nxt][kk + 0][lm] = f2tf32(pb[r].x);
                Bs[nxt][kk + 1][lm] = f2tf32(pb[r].y);
                Bs[nxt][kk + 2][lm] = f2tf32(pb[r].z);
                Bs[nxt][kk + 3][lm] = f2tf32(pb[r].w);
            }
        }
        __syncthreads();
    }

    // ---- epilogue: bias + store ----
#pragma unroll
    for (int i = 0; i < 2; i++) {
        const int m0 = by * 128 + wm * 32 + i * 16 + gid;
#pragma unroll
        for (int j = 0; j < 8; j++) {
            const int n = bx * 128 + wn * 64 + j * 8 + tig * 2;
            const float b0 = __ldg(bias + n);
            const float b1 = __ldg(bias + n + 1);
            float2 v0, v1;
            v0.x = acc[i][j][0] + b0;  v0.y = acc[i][j][1] + b1;
            v1.x = acc[i][j][2] + b0;  v1.y = acc[i][j][3] + b1;
            *(float2*)(C + (size_t)m0 * N + n)       = v0;
            *(float2*)(C + (size_t)(m0 + 8) * N + n) = v1;
        }
    }
}

// =============================================================================
// Persistent GRU recurrence. Cluster of 4 CTAs handles 8 batch rows.
// CTA rank r owns hidden columns [r*64, r*64+64): 192 W_hh rows in SMEM.
// h double-buffered in SMEM, DSMEM broadcast, 1 cluster.sync/step.
// =============================================================================
#define WT_PITCH 193
#define REC_SMEM_FLOATS (256 * WT_PITCH + 2 * 256 * 8 + 8 * 192 + 192)

__global__ void __cluster_dims__(4, 1, 1) __launch_bounds__(128, 1)
gru_rec(const float* __restrict__ Whh, const float* __restrict__ bhh_g,
        const float* __restrict__ gi, float* __restrict__ hout, int store_all)
{
    extern __shared__ float smf[];
    float* Wt   = smf;                         // [256][193]
    float* hbuf = Wt + 256 * WT_PITCH;         // [2][256][8]
    float* gh   = hbuf + 2 * 256 * 8;          // [8][192]
    float* bhh  = gh + 8 * 192;                // [192]

    cg::cluster_group cluster = cg::this_cluster();
    const int rank = cluster.block_rank();
    const int cid  = blockIdx.x >> 2;
    const int B0   = cid * 8;

    const int t  = threadIdx.x;
    const int jj = t & 63;
    const int gb = t >> 6;

    for (int rr = 0; rr < 192; rr++) {
        const int grow = ((rr >> 6) << 8) + rank * 64 + (rr & 63);
        const float* wr = Whh + (size_t)grow * HID;
        for (int k = t; k < 256; k += 128) Wt[k * WT_PITCH + rr] = wr[k];
    }
    for (int rr = t; rr < 192; rr += 128)
        bhh[rr] = bhh_g[((rr >> 6) << 8) + rank * 64 + (rr & 63)];
    for (int i = t; i < 2 * 256 * 8; i += 128) hbuf[i] = 0.0f;
    __syncthreads();
    cluster.sync();

    const int kglob = rank * 64 + jj;

    for (int ts = 0; ts < T_STEPS; ts++) {
        const int p = ts & 1;
        const float* hrd = hbuf + p * 2048;

        float gv[12];
        {
            const float* gbase = gi + ((size_t)ts * BATCH + B0) * G3 + rank * 64 + jj;
#pragma unroll
            for (int i = 0; i < 4; i++) {
                const int b = gb + 2 * i;
                const float* gp = gbase + (size_t)b * G3;
                gv[i * 3 + 0] = __ldg(gp);
                gv[i * 3 + 1] = __ldg(gp + 256);
                gv[i * 3 + 2] = __ldg(gp + 512);
            }
        }

        float a0 = 0, a1 = 0, a2 = 0, a3 = 0, a4 = 0, a5 = 0;
        float a6 = 0, a7 = 0, a8 = 0, a9 = 0, a10 = 0, a11 = 0;
        const float* hp = hrd + gb * 4;
#pragma unroll 4
        for (int k = 0; k < 256; k++) {
            const float4 h4 = *(const float4*)(hp + (k << 3));
            const float w0 = Wt[k * WT_PITCH + jj];
            const float w1 = Wt[k * WT_PITCH + 64 + jj];
            const float w2 = Wt[k * WT_PITCH + 128 + jj];
            a0 += w0 * h4.x; a1 += w0 * h4.y; a2  += w0 * h4.z; a3  += w0 * h4.w;
            a4 += w1 * h4.x; a5 += w1 * h4.y; a6  += w1 * h4.z; a7  += w1 * h4.w;
            a8 += w2 * h4.x; a9 += w2 * h4.y; a10 += w2 * h4.z; a11 += w2 * h4.w;
        }
        {
            const int bb = gb * 4;
            gh[(bb + 0) * 192 +       jj] = a0;
            gh[(bb + 1) * 192 +       jj] = a1;
            gh[(bb + 2) * 192 +       jj] = a2;
            gh[(bb + 3) * 192 +       jj] = a3;
            gh[(bb + 0) * 192 +  64 + jj] = a4;
            gh[(bb + 1) * 192 +  64 + jj] = a5;
            gh[(bb + 2) * 192 +  64 + jj] = a6;
            gh[(bb + 3) * 192 +  64 + jj] = a7;
            gh[(bb + 0) * 192 + 128 + jj] = a8;
            gh[(bb + 1) * 192 + 128 + jj] = a9;
            gh[(bb + 2) * 192 + 128 + jj] = a10;
            gh[(bb + 3) * 192 + 128 + jj] = a11;
        }
        __syncthreads();

        float* hwr = hbuf + (p ^ 1) * 2048;
        const float br = bhh[jj], bz = bhh[64 + jj], bn = bhh[128 + jj];
#pragma unroll
        for (int i = 0; i < 4; i++) {
            const int b = gb + 2 * i;
            const float hr = gh[b * 192 + jj]       + br;
            const float hz = gh[b * 192 + 64 + jj]  + bz;
            const float hn = gh[b * 192 + 128 + jj] + bn;
            const float r  = __fdividef(1.0f, 1.0f + __expf(-(gv[i * 3 + 0] + hr)));
            const float z  = __fdividef(1.0f, 1.0f + __expf(-(gv[i * 3 + 1] + hz)));
            const float n  = tanhf(gv[i * 3 + 2] + r * hn);
            const float hprev = hrd[(kglob << 3) + b];
            const float hnew  = (1.0f - z) * n + z * hprev;

            float* lp = hwr + (kglob << 3) + b;
#pragma unroll
            for (int q = 0; q < 4; q++) {
                float* dp = (float*)cluster.map_shared_rank(lp, q);
                *dp = hnew;
            }
            if (store_all) {
                hout[((size_t)ts * BATCH + B0 + b) * HID + kglob] = hnew;
            } else if (ts == T_STEPS - 1) {
                hout[(size_t)(B0 + b) * HID + kglob] = hnew;
            }
        }
        cluster.sync();
    }
}

// =============================================================================
// FC on the last hidden state
// =============================================================================
__global__ __launch_bounds__(256) void fc_kernel(
    const float* __restrict__ Wfc, const float* __restrict__ bfc,
    float* __restrict__ out)
{
    __shared__ float hs[256];
    const int b = blockIdx.x;
    const int o = threadIdx.x;
    hs[o] = g_h2[b * 256 + o];
    __syncthreads();
    const float* wr = Wfc + (size_t)o * 256;
    float acc = 0.0f;
#pragma unroll 8
    for (int k = 0; k < 256; k += 4) {
        const float4 w = *(const float4*)(wr + k);
        acc += hs[k] * w.x + hs[k + 1] * w.y + hs[k + 2] * w.z + hs[k + 3] * w.w;
    }
    out[b * 256 + o] = acc + bfc[o];
}

// =============================================================================
extern "C" void kernel_launch(void* const* d_in, const int* in_sizes, int n_in,
                              void* d_out, int out_size)
{
    const float* x     = (const float*)d_in[0];
    const float* W_ih0 = (const float*)d_in[1];
    const float* W_hh0 = (const float*)d_in[2];
    const float* b_ih0 = (const float*)d_in[3];
    const float* b_hh0 = (const float*)d_in[4];
    const float* W_ih1 = (const float*)d_in[5];
    const float* W_hh1 = (const float*)d_in[6];
    const float* b_ih1 = (const float*)d_in[7];
    const float* b_hh1 = (const float*)d_in[8];
    const float* W_fc  = (const float*)d_in[9];
    const float* b_fc  = (const float*)d_in[10];
    float* out = (float*)d_out;

    float *gi_p, *h1_p, *h2_p;
    cudaGetSymbolAddress((void**)&gi_p, g_gi);
    cudaGetSymbolAddress((void**)&h1_p, g_h1);
    cudaGetSymbolAddress((void**)&h2_p, g_h2);

    const size_t REC_SMEM = REC_SMEM_FLOATS * sizeof(float);
    cudaFuncSetAttribute(gru_rec, cudaFuncAttributeMaxDynamicSharedMemorySize,
                         (int)REC_SMEM);

    const int M = T_STEPS * BATCH;        // 131072
    dim3 gemm_grid(G3 / 128, M / 128);    // (6, 1024)

    // layer 0: gi0 = x @ W_ih0^T + b_ih0   (tf32 HMMA, K=128)
    gemm_tf32mma<<<gemm_grid, 256>>>(x, W_ih0, b_ih0, gi_p, G3, IN0);
    // layer 0 recurrence -> g_h1[T,B,H]
    gru_rec<<<128, 128, REC_SMEM>>>(W_hh0, b_hh0, gi_p, h1_p, 1);
    // layer 1: gi1 = h1 @ W_ih1^T + b_ih1  (tf32 HMMA, K=256)
    gemm_tf32mma<<<gemm_grid, 256>>>(h1_p, W_ih1, b_ih1, gi_p, G3, HID);
    // layer 1 recurrence -> g_h2[B,H]
    gru_rec<<<128, 128, REC_SMEM>>>(W_hh1, b_hh1, gi_p, h2_p, 0);
    // FC head
    fc_kernel<<<BATCH, 256>>>(W_fc, b_fc, out);
}

// round 5
// speedup vs baseline: 1.6764x; 1.5198x over previous
#include <cuda_runtime.h>
#include <cooperative_groups.h>
#include <cstdint>

namespace cg = cooperative_groups;

#define T_STEPS 512
#define BATCH   256
#define IN0     128
#define HID     256
#define G3      768   // 3*HID

// ---------------- scratch (static device arrays; allocation-free) ------------
__device__ float g_gi[(size_t)T_STEPS * BATCH * G3];   // reused by both layers
__device__ float g_h1[(size_t)T_STEPS * BATCH * HID];  // layer-0 outputs
__device__ float g_h2[BATCH * HID];                    // final hidden state

// ======================= helpers ========================
__device__ __forceinline__ float f2tf32(float x) {
    float r;
    asm("cvt.rna.tf32.f32 %0, %1;" : "=f"(r) : "f"(x));
    return r;
}

__device__ __forceinline__ void mma_tf32(float* d, const float* a, const float* b) {
    asm volatile(
        "mma.sync.aligned.m16n8k8.row.col.f32.tf32.tf32.f32 "
        "{%0,%1,%2,%3}, {%4,%5,%6,%7}, {%8,%9}, {%0,%1,%2,%3};"
        : "+f"(d[0]), "+f"(d[1]), "+f"(d[2]), "+f"(d[3])
        : "r"(__float_as_uint(a[0])), "r"(__float_as_uint(a[1])),
          "r"(__float_as_uint(a[2])), "r"(__float_as_uint(a[3])),
          "r"(__float_as_uint(b[0])), "r"(__float_as_uint(b[1])));
}

__device__ __forceinline__ void cp_async16(uint32_t dst, const void* src) {
    asm volatile("cp.async.cg.shared.global [%0], [%1], 16;"
                 :: "r"(dst), "l"(src) : "memory");
}

// =============================================================================
// HMMA tf32 GEMM:  C[M,N] = A[M,K] @ Bw[N,K]^T + bias[N]
// (validated round 4; unchanged)
// =============================================================================
#define PITCH 136

__global__ __launch_bounds__(256, 2) void gemm_tf32mma(
    const float* __restrict__ A, const float* __restrict__ Bw,
    const float* __restrict__ bias, float* __restrict__ C,
    int N, int K)
{
    __shared__ float As[2][16][PITCH];
    __shared__ float Bs[2][16][PITCH];

    const int t    = threadIdx.x;
    const int bx   = blockIdx.x;
    const int by   = blockIdx.y;
    const int lane = t & 31;
    const int w    = t >> 5;
    const int wm   = w & 3;
    const int wn   = w >> 2;
    const int gid  = lane >> 2;
    const int tig  = lane & 3;

    const float* Ab = A  + (size_t)(by * 128) * K;
    const float* Bb = Bw + (size_t)(bx * 128) * K;

    const int lm = t & 127;
    const int f0 = (t >> 7) * 2;

    float acc[2][8][4];
#pragma unroll
    for (int i = 0; i < 2; i++)
#pragma unroll
        for (int j = 0; j < 8; j++)
#pragma unroll
            for (int q = 0; q < 4; q++) acc[i][j][q] = 0.0f;

    float4 pa[2], pb[2];
#pragma unroll
    for (int r = 0; r < 2; r++) {
        pa[r] = *(const float4*)(Ab + (size_t)lm * K + (f0 + r) * 4);
        pb[r] = *(const float4*)(Bb + (size_t)lm * K + (f0 + r) * 4);
    }
#pragma unroll
    for (int r = 0; r < 2; r++) {
        const int kk = (f0 + r) * 4;
        As[0][kk + 0][lm] = f2tf32(pa[r].x);
        As[0][kk + 1][lm] = f2tf32(pa[r].y);
        As[0][kk + 2][lm] = f2tf32(pa[r].z);
        As[0][kk + 3][lm] = f2tf32(pa[r].w);
        Bs[0][kk + 0][lm] = f2tf32(pb[r].x);
        Bs[0][kk + 1][lm] = f2tf32(pb[r].y);
        Bs[0][kk + 2][lm] = f2tf32(pb[r].z);
        Bs[0][kk + 3][lm] = f2tf32(pb[r].w);
    }
    __syncthreads();

    const int nst = K >> 4;
    for (int s = 0; s < nst; s++) {
        const int cur = s & 1;
        const bool pf = (s + 1 < nst);
        if (pf) {
            const int kbase = (s + 1) * 16;
#pragma unroll
            for (int r = 0; r < 2; r++) {
                pa[r] = *(const float4*)(Ab + (size_t)lm * K + kbase + (f0 + r) * 4);
                pb[r] = *(const float4*)(Bb + (size_t)lm * K + kbase + (f0 + r) * 4);
            }
        }
#pragma unroll
        for (int kk = 0; kk < 16; kk += 8) {
            float a[2][4], b[8][2];
#pragma unroll
            for (int i = 0; i < 2; i++) {
                const int m = wm * 32 + i * 16 + gid;
                a[i][0] = As[cur][kk + tig][m];
                a[i][1] = As[cur][kk + tig][m + 8];
                a[i][2] = As[cur][kk + tig + 4][m];
                a[i][3] = As[cur][kk + tig + 4][m + 8];
            }
#pragma unroll
            for (int j = 0; j < 8; j++) {
                const int n = wn * 64 + j * 8 + gid;
                b[j][0] = Bs[cur][kk + tig][n];
                b[j][1] = Bs[cur][kk + tig + 4][n];
            }
#pragma unroll
            for (int i = 0; i < 2; i++)
#pragma unroll
                for (int j = 0; j < 8; j++)
                    mma_tf32(acc[i][j], a[i], b[j]);
        }
        if (pf) {
            const int nxt = cur ^ 1;
#pragma unroll
            for (int r = 0; r < 2; r++) {
                const int kk = (f0 + r) * 4;
                As[nxt][kk + 0][lm] = f2tf32(pa[r].x);
                As[nxt][kk + 1][lm] = f2tf32(pa[r].y);
                As[nxt][kk + 2][lm] = f2tf32(pa[r].z);
                As[nxt][kk + 3][lm] = f2tf32(pa[r].w);
                Bs[nxt][kk + 0][lm] = f2tf32(pb[r].x);
                Bs[nxt][kk + 1][lm] = f2tf32(pb[r].y);
                Bs[nxt][kk + 2][lm] = f2tf32(pb[r].z);
                Bs[nxt][kk + 3][lm] = f2tf32(pb[r].w);
            }
        }
        __syncthreads();
    }

#pragma unroll
    for (int i = 0; i < 2; i++) {
        const int m0 = by * 128 + wm * 32 + i * 16 + gid;
#pragma unroll
        for (int j = 0; j < 8; j++) {
            const int n = bx * 128 + wn * 64 + j * 8 + tig * 2;
            const float b0 = __ldg(bias + n);
            const float b1 = __ldg(bias + n + 1);
            float2 v0, v1;
            v0.x = acc[i][j][0] + b0;  v0.y = acc[i][j][1] + b1;
            v1.x = acc[i][j][2] + b0;  v1.y = acc[i][j][3] + b1;
            *(float2*)(C + (size_t)m0 * N + n)       = v0;
            *(float2*)(C + (size_t)(m0 + 8) * N + n) = v1;
        }
    }
}

// =============================================================================
// HMMA-based persistent GRU recurrence.
// Cluster of 4 CTAs = 8 batch rows. CTA rank owns hidden cols [r*64,(r+1)*64)
// = 192 gate rows of W_hh, held ENTIRELY IN REGISTERS as tf32 MMA fragments
// (warp w of 12 owns m-tile w: rows [16w,16w+16), all 32 k-steps, 128 regs).
// Per step: D[192x8] = W @ h^T via 2-term tf32 split (exact-h error killed);
// gi streamed into SMEM via cp.async; gates by warps 0..7; DSMEM h broadcast.
// =============================================================================
#define HP 12   // hbuf pitch (floats): conflict-free for B-fragment pattern

__global__ void __cluster_dims__(4, 1, 1) __launch_bounds__(384, 1)
gru_rec_mma(const float* __restrict__ Whh, const float* __restrict__ bhh_g,
            const float* __restrict__ gi, float* __restrict__ hout,
            int store_all)
{
    __shared__ float hbuf[2][256 * HP];   // h state, k-major [k][batch], pitch 12
    __shared__ float gh[8 * 200];         // W@h result, [batch][192 gate-rows] pitch 200
    __shared__ float gi_s[8 * 192];       // this step's gi slice [batch][192]
    __shared__ float bhh[192];

    cg::cluster_group cluster = cg::this_cluster();
    const int rank = cluster.block_rank();
    const int B0   = (blockIdx.x >> 2) * 8;

    const int t    = threadIdx.x;
    const int lane = t & 31;
    const int w    = t >> 5;              // 0..11
    const int gid  = lane >> 2;           // 0..7
    const int tig  = lane & 3;            // 0..3

    // ---- W_hh fragments -> registers (once) ----
    float wa0[32], wa1[32], wa2[32], wa3[32];
    {
        const int g  = w >> 2;                                // gate block 0..2
        const int r0 = g * 256 + rank * 64 + (w & 3) * 16 + gid;
        const float* p0 = Whh + (size_t)r0 * 256;
        const float* p1 = p0 + 8 * 256;
#pragma unroll
        for (int s = 0; s < 32; s++) {
            wa0[s] = f2tf32(p0[8 * s + tig]);
            wa1[s] = f2tf32(p1[8 * s + tig]);
            wa2[s] = f2tf32(p0[8 * s + tig + 4]);
            wa3[s] = f2tf32(p1[8 * s + tig + 4]);
        }
    }
    for (int i = t; i < 192; i += 384)
        bhh[i] = bhh_g[((i >> 6) << 8) + rank * 64 + (i & 63)];
    for (int i = t; i < 2 * 256 * HP; i += 384) ((float*)hbuf)[i] = 0.0f;
    __syncthreads();
    cluster.sync();

    // gate-phase identity (threads 0..255)
    const int j     = t & 63;
    const int bb    = (t >> 6) & 3;
    const int kglob = rank * 64 + j;

    // cp.async chunk identity (all 384 threads, 16B each, 1536 floats total)
    const int cb   = t / 48;              // batch 0..7
    const int crem = t % 48;
    const int cg_  = crem >> 4;           // gate 0..2
    const int cq   = crem & 15;           // 4-float group 0..15
    const uint32_t gis_dst = (uint32_t)__cvta_generic_to_shared(
        &gi_s[cb * 192 + cg_ * 64 + cq * 4]);
    const float* gi_src0 = gi + ((size_t)B0 + cb) * G3 + cg_ * 256 + rank * 64 + cq * 4;

    for (int ts = 0; ts < T_STEPS; ts++) {
        const int p = ts & 1;
        const float* hrd = hbuf[p];

        // ---- stream this step's gi slice into SMEM (latency hidden by GEMM) --
        cp_async16(gis_dst, gi_src0 + (size_t)ts * BATCH * G3);
        asm volatile("cp.async.commit_group;" ::: "memory");

        // ---- GEMM: D[192x8] = W @ h^T, 2-term tf32 split ----
        float aE[4] = {0, 0, 0, 0}, aO[4] = {0, 0, 0, 0};
        const float* hb = hrd + tig * HP + gid;
#pragma unroll
        for (int s = 0; s < 32; s++) {
            const float v0 = hb[s * 8 * HP];
            const float v1 = hb[s * 8 * HP + 4 * HP];
            const float hi0 = f2tf32(v0), hi1 = f2tf32(v1);
            float bh[2] = {hi0, hi1};
            float bl[2] = {f2tf32(v0 - hi0), f2tf32(v1 - hi1)};
            float wv[4] = {wa0[s], wa1[s], wa2[s], wa3[s]};
            if (s & 1) { mma_tf32(aO, wv, bh); mma_tf32(aO, wv, bl); }
            else       { mma_tf32(aE, wv, bh); mma_tf32(aE, wv, bl); }
        }
        {   // write D tile to gh[batch][gate-row]
            const int lr = w * 16 + gid;
            const int b0 = tig * 2;
            gh[(b0    ) * 200 + lr    ] = aE[0] + aO[0];
            gh[(b0 + 1) * 200 + lr    ] = aE[1] + aO[1];
            gh[(b0    ) * 200 + lr + 8] = aE[2] + aO[2];
            gh[(b0 + 1) * 200 + lr + 8] = aE[3] + aO[3];
        }
        asm volatile("cp.async.wait_group 0;" ::: "memory");
        __syncthreads();

        // ---- gates + h update + DSMEM broadcast (threads 0..255) ----
        if (t < 256) {
            float* hwr = hbuf[p ^ 1];
            const float br = bhh[j], bz = bhh[64 + j], bn = bhh[128 + j];
#pragma unroll
            for (int i = 0; i < 2; i++) {
                const int b = bb + 4 * i;
                const float hr = gh[b * 200 + j]       + br;
                const float hz = gh[b * 200 + 64 + j]  + bz;
                const float hn = gh[b * 200 + 128 + j] + bn;
                const float ir = gi_s[b * 192 + j];
                const float iz = gi_s[b * 192 + 64 + j];
                const float in_ = gi_s[b * 192 + 128 + j];
                const float r = __fdividef(1.0f, 1.0f + __expf(-(ir + hr)));
                const float z = __fdividef(1.0f, 1.0f + __expf(-(iz + hz)));
                const float n = tanhf(in_ + r * hn);
                const float hprev = hrd[kglob * HP + b];
                const float hnew  = (1.0f - z) * n + z * hprev;

                float* lp = hwr + kglob * HP + b;
#pragma unroll
                for (int q = 0; q < 4; q++)
                    *(float*)cluster.map_shared_rank(lp, q) = hnew;

                if (store_all) {
                    hout[((size_t)ts * BATCH + B0 + b) * HID + kglob] = hnew;
                } else if (ts == T_STEPS - 1) {
                    hout[(size_t)(B0 + b) * HID + kglob] = hnew;
                }
            }
        }
        cluster.sync();
    }
}

// =============================================================================
// FC on the last hidden state
// =============================================================================
__global__ __launch_bounds__(256) void fc_kernel(
    const float* __restrict__ Wfc, const float* __restrict__ bfc,
    float* __restrict__ out)
{
    __shared__ float hs[256];
    const int b = blockIdx.x;
    const int o = threadIdx.x;
    hs[o] = g_h2[b * 256 + o];
    __syncthreads();
    const float* wr = Wfc + (size_t)o * 256;
    float acc = 0.0f;
#pragma unroll 8
    for (int k = 0; k < 256; k += 4) {
        const float4 wv = *(const float4*)(wr + k);
        acc += hs[k] * wv.x + hs[k + 1] * wv.y + hs[k + 2] * wv.z + hs[k + 3] * wv.w;
    }
    out[b * 256 + o] = acc + bfc[o];
}

// =============================================================================
extern "C" void kernel_launch(void* const* d_in, const int* in_sizes, int n_in,
                              void* d_out, int out_size)
{
    const float* x     = (const float*)d_in[0];
    const float* W_ih0 = (const float*)d_in[1];
    const float* W_hh0 = (const float*)d_in[2];
    const float* b_ih0 = (const float*)d_in[3];
    const float* b_hh0 = (const float*)d_in[4];
    const float* W_ih1 = (const float*)d_in[5];
    const float* W_hh1 = (const float*)d_in[6];
    const float* b_ih1 = (const float*)d_in[7];
    const float* b_hh1 = (const float*)d_in[8];
    const float* W_fc  = (const float*)d_in[9];
    const float* b_fc  = (const float*)d_in[10];
    float* out = (float*)d_out;

    float *gi_p, *h1_p, *h2_p;
    cudaGetSymbolAddress((void**)&gi_p, g_gi);
    cudaGetSymbolAddress((void**)&h1_p, g_h1);
    cudaGetSymbolAddress((void**)&h2_p, g_h2);

    const int M = T_STEPS * BATCH;        // 131072
    dim3 gemm_grid(G3 / 128, M / 128);    // (6, 1024)

    // layer 0: gi0 = x @ W_ih0^T + b_ih0   (tf32 HMMA, K=128)
    gemm_tf32mma<<<gemm_grid, 256>>>(x, W_ih0, b_ih0, gi_p, G3, IN0);
    // layer 0 recurrence -> g_h1[T,B,H]
    gru_rec_mma<<<128, 384>>>(W_hh0, b_hh0, gi_p, h1_p, 1);
    // layer 1: gi1 = h1 @ W_ih1^T + b_ih1  (tf32 HMMA, K=256)
    gemm_tf32mma<<<gemm_grid, 256>>>(h1_p, W_ih1, b_ih1, gi_p, G3, HID);
    // layer 1 recurrence -> g_h2[B,H]
    gru_rec_mma<<<128, 384>>>(W_hh1, b_hh1, gi_p, h2_p, 0);
    // FC head
    fc_kernel<<<BATCH, 256>>>(W_fc, b_fc, out);
}

// round 6
// speedup vs baseline: 2.0225x; 1.2064x over previous
#include <cuda_runtime.h>
#include <cooperative_groups.h>
#include <cstdint>

namespace cg = cooperative_groups;

#define T_STEPS 512
#define BATCH   256
#define IN0     128
#define HID     256
#define G3      768   // 3*HID

// ---------------- scratch (static device arrays; allocation-free) ------------
__device__ float g_gi[(size_t)T_STEPS * BATCH * G3];   // reused by both layers
__device__ float g_h1[(size_t)T_STEPS * BATCH * HID];  // layer-0 outputs
__device__ float g_h2[BATCH * HID];                    // final hidden state

// ======================= helpers ========================
__device__ __forceinline__ float f2tf32(float x) {
    float r;
    asm("cvt.rna.tf32.f32 %0, %1;" : "=f"(r) : "f"(x));
    return r;
}

__device__ __forceinline__ void mma_tf32(float* d, const float* a, const float* b) {
    asm volatile(
        "mma.sync.aligned.m16n8k8.row.col.f32.tf32.tf32.f32 "
        "{%0,%1,%2,%3}, {%4,%5,%6,%7}, {%8,%9}, {%0,%1,%2,%3};"
        : "+f"(d[0]), "+f"(d[1]), "+f"(d[2]), "+f"(d[3])
        : "r"(__float_as_uint(a[0])), "r"(__float_as_uint(a[1])),
          "r"(__float_as_uint(a[2])), "r"(__float_as_uint(a[3])),
          "r"(__float_as_uint(b[0])), "r"(__float_as_uint(b[1])));
}

__device__ __forceinline__ void cp_async16(uint32_t dst, const void* src) {
    asm volatile("cp.async.cg.shared.global [%0], [%1], 16;"
                 :: "r"(dst), "l"(src) : "memory");
}

__device__ __forceinline__ float tanh_fast(float x) {
    float r;
    asm("tanh.approx.f32 %0, %1;" : "=f"(r) : "f"(x));
    return r;
}

// =============================================================================
// HMMA tf32 GEMM:  C[M,N] = A[M,K] @ Bw[N,K]^T + bias[N]   (validated R4)
// =============================================================================
#define PITCH 136

__global__ __launch_bounds__(256, 2) void gemm_tf32mma(
    const float* __restrict__ A, const float* __restrict__ Bw,
    const float* __restrict__ bias, float* __restrict__ C,
    int N, int K)
{
    __shared__ float As[2][16][PITCH];
    __shared__ float Bs[2][16][PITCH];

    const int t    = threadIdx.x;
    const int bx   = blockIdx.x;
    const int by   = blockIdx.y;
    const int lane = t & 31;
    const int w    = t >> 5;
    const int wm   = w & 3;
    const int wn   = w >> 2;
    const int gid  = lane >> 2;
    const int tig  = lane & 3;

    const float* Ab = A  + (size_t)(by * 128) * K;
    const float* Bb = Bw + (size_t)(bx * 128) * K;

    const int lm = t & 127;
    const int f0 = (t >> 7) * 2;

    float acc[2][8][4];
#pragma unroll
    for (int i = 0; i < 2; i++)
#pragma unroll
        for (int jx = 0; jx < 8; jx++)
#pragma unroll
            for (int q = 0; q < 4; q++) acc[i][jx][q] = 0.0f;

    float4 pa[2], pb[2];
#pragma unroll
    for (int r = 0; r < 2; r++) {
        pa[r] = *(const float4*)(Ab + (size_t)lm * K + (f0 + r) * 4);
        pb[r] = *(const float4*)(Bb + (size_t)lm * K + (f0 + r) * 4);
    }
#pragma unroll
    for (int r = 0; r < 2; r++) {
        const int kk = (f0 + r) * 4;
        As[0][kk + 0][lm] = f2tf32(pa[r].x);
        As[0][kk + 1][lm] = f2tf32(pa[r].y);
        As[0][kk + 2][lm] = f2tf32(pa[r].z);
        As[0][kk + 3][lm] = f2tf32(pa[r].w);
        Bs[0][kk + 0][lm] = f2tf32(pb[r].x);
        Bs[0][kk + 1][lm] = f2tf32(pb[r].y);
        Bs[0][kk + 2][lm] = f2tf32(pb[r].z);
        Bs[0][kk + 3][lm] = f2tf32(pb[r].w);
    }
    __syncthreads();

    const int nst = K >> 4;
    for (int s = 0; s < nst; s++) {
        const int cur = s & 1;
        const bool pf = (s + 1 < nst);
        if (pf) {
            const int kbase = (s + 1) * 16;
#pragma unroll
            for (int r = 0; r < 2; r++) {
                pa[r] = *(const float4*)(Ab + (size_t)lm * K + kbase + (f0 + r) * 4);
                pb[r] = *(const float4*)(Bb + (size_t)lm * K + kbase + (f0 + r) * 4);
            }
        }
#pragma unroll
        for (int kk = 0; kk < 16; kk += 8) {
            float a[2][4], b[8][2];
#pragma unroll
            for (int i = 0; i < 2; i++) {
                const int m = wm * 32 + i * 16 + gid;
                a[i][0] = As[cur][kk + tig][m];
                a[i][1] = As[cur][kk + tig][m + 8];
                a[i][2] = As[cur][kk + tig + 4][m];
                a[i][3] = As[cur][kk + tig + 4][m + 8];
            }
#pragma unroll
            for (int jx = 0; jx < 8; jx++) {
                const int n = wn * 64 + jx * 8 + gid;
                b[jx][0] = Bs[cur][kk + tig][n];
                b[jx][1] = Bs[cur][kk + tig + 4][n];
            }
#pragma unroll
            for (int i = 0; i < 2; i++)
#pragma unroll
                for (int jx = 0; jx < 8; jx++)
                    mma_tf32(acc[i][jx], a[i], b[jx]);
        }
        if (pf) {
            const int nxt = cur ^ 1;
#pragma unroll
            for (int r = 0; r < 2; r++) {
                const int kk = (f0 + r) * 4;
                As[nxt][kk + 0][lm] = f2tf32(pa[r].x);
                As[nxt][kk + 1][lm] = f2tf32(pa[r].y);
                As[nxt][kk + 2][lm] = f2tf32(pa[r].z);
                As[nxt][kk + 3][lm] = f2tf32(pa[r].w);
                Bs[nxt][kk + 0][lm] = f2tf32(pb[r].x);
                Bs[nxt][kk + 1][lm] = f2tf32(pb[r].y);
                Bs[nxt][kk + 2][lm] = f2tf32(pb[r].z);
                Bs[nxt][kk + 3][lm] = f2tf32(pb[r].w);
            }
        }
        __syncthreads();
    }

#pragma unroll
    for (int i = 0; i < 2; i++) {
        const int m0 = by * 128 + wm * 32 + i * 16 + gid;
#pragma unroll
        for (int jx = 0; jx < 8; jx++) {
            const int n = bx * 128 + wn * 64 + jx * 8 + tig * 2;
            const float b0 = __ldg(bias + n);
            const float b1 = __ldg(bias + n + 1);
            float2 v0, v1;
            v0.x = acc[i][jx][0] + b0;  v0.y = acc[i][jx][1] + b1;
            v1.x = acc[i][jx][2] + b0;  v1.y = acc[i][jx][3] + b1;
            *(float2*)(C + (size_t)m0 * N + n)       = v0;
            *(float2*)(C + (size_t)(m0 + 8) * N + n) = v1;
        }
    }
}

// =============================================================================
// HMMA persistent GRU recurrence, v2:
//  - exact h state lives in fp32 REGISTERS of the owning thread (hprev0/1);
//    hbuf holds the tf32-rounded MMA operand only -> no per-step cvt chain,
//    single-term MMA (384 HMMA/CTA/step, half of v1).
//  - 4 independent accumulator chains (s%4) -> dependency depth 8.
//  - hbuf pitch 9: gate-phase writes conflict-free (gcd(9,32)=1).
// =============================================================================
#define HP 9

__global__ void __cluster_dims__(4, 1, 1) __launch_bounds__(384, 1)
gru_rec_mma(const float* __restrict__ Whh, const float* __restrict__ bhh_g,
            const float* __restrict__ gi, float* __restrict__ hout,
            int store_all)
{
    __shared__ float hbuf[2][256 * HP];   // tf32 h operand, [k][batch] pitch 9
    __shared__ float gh[8 * 200];         // W@h, [batch][192 gate-rows] pitch 200
    __shared__ float gi_s[8 * 192];       // this step's gi slice [batch][192]
    __shared__ float bhh[192];

    cg::cluster_group cluster = cg::this_cluster();
    const int rank = cluster.block_rank();
    const int B0   = (blockIdx.x >> 2) * 8;

    const int t    = threadIdx.x;
    const int lane = t & 31;
    const int w    = t >> 5;              // 0..11
    const int gid  = lane >> 2;           // 0..7
    const int tig  = lane & 3;            // 0..3

    // ---- W_hh fragments -> registers (once): warp w owns m-tile w ----
    float wa0[32], wa1[32], wa2[32], wa3[32];
    {
        const int g  = w >> 2;                                // gate block 0..2
        const int r0 = g * 256 + rank * 64 + (w & 3) * 16 + gid;
        const float* p0 = Whh + (size_t)r0 * 256;
        const float* p1 = p0 + 8 * 256;
#pragma unroll
        for (int s = 0; s < 32; s++) {
            wa0[s] = f2tf32(p0[8 * s + tig]);
            wa1[s] = f2tf32(p1[8 * s + tig]);
            wa2[s] = f2tf32(p0[8 * s + tig + 4]);
            wa3[s] = f2tf32(p1[8 * s + tig + 4]);
        }
    }
    for (int i = t; i < 192; i += 384)
        bhh[i] = bhh_g[((i >> 6) << 8) + rank * 64 + (i & 63)];
    for (int i = t; i < 2 * 256 * HP; i += 384) ((float*)hbuf)[i] = 0.0f;
    __syncthreads();
    cluster.sync();

    // gate-phase identity (threads 0..255): thread owns (j, bb) and (j, bb+4)
    const int j     = t & 63;
    const int bb    = (t >> 6) & 3;
    const int kglob = rank * 64 + j;
    float hprev0 = 0.0f, hprev1 = 0.0f;    // EXACT fp32 state, register-resident

    // cp.async chunk identity (all 384 threads, 16B each)
    const int cb   = t / 48;
    const int crem = t % 48;
    const int cg_  = crem >> 4;
    const int cq   = crem & 15;
    const uint32_t gis_dst = (uint32_t)__cvta_generic_to_shared(
        &gi_s[cb * 192 + cg_ * 64 + cq * 4]);
    const float* gi_src0 = gi + ((size_t)B0 + cb) * G3 + cg_ * 256 + rank * 64 + cq * 4;

    for (int ts = 0; ts < T_STEPS; ts++) {
        const int p = ts & 1;
        const float* hrd = hbuf[p];

        // ---- stream this step's gi slice (latency hidden under the GEMM) ----
        cp_async16(gis_dst, gi_src0 + (size_t)ts * BATCH * G3);
        asm volatile("cp.async.commit_group;" ::: "memory");

        // ---- GEMM: D[192x8] = W @ h^T, single tf32 term, 4 acc chains ----
        float c0[4] = {0, 0, 0, 0}, c1[4] = {0, 0, 0, 0};
        float c2[4] = {0, 0, 0, 0}, c3[4] = {0, 0, 0, 0};
        const float* hb = hrd + tig * HP + gid;
#pragma unroll
        for (int s = 0; s < 32; s += 4) {
            float b0[2] = { hb[(s + 0) * 8 * HP], hb[(s + 0) * 8 * HP + 4 * HP] };
            float b1[2] = { hb[(s + 1) * 8 * HP], hb[(s + 1) * 8 * HP + 4 * HP] };
            float b2[2] = { hb[(s + 2) * 8 * HP], hb[(s + 2) * 8 * HP + 4 * HP] };
            float b3[2] = { hb[(s + 3) * 8 * HP], hb[(s + 3) * 8 * HP + 4 * HP] };
            float w0[4] = { wa0[s + 0], wa1[s + 0], wa2[s + 0], wa3[s + 0] };
            float w1[4] = { wa0[s + 1], wa1[s + 1], wa2[s + 1], wa3[s + 1] };
            float w2[4] = { wa0[s + 2], wa1[s + 2], wa2[s + 2], wa3[s + 2] };
            float w3[4] = { wa0[s + 3], wa1[s + 3], wa2[s + 3], wa3[s + 3] };
            mma_tf32(c0, w0, b0);
            mma_tf32(c1, w1, b1);
            mma_tf32(c2, w2, b2);
            mma_tf32(c3, w3, b3);
        }
        {   // combine chains, write D tile to gh[batch][gate-row]
            const int lr = w * 16 + gid;
            const int b0i = tig * 2;
            gh[(b0i    ) * 200 + lr    ] = (c0[0] + c1[0]) + (c2[0] + c3[0]);
            gh[(b0i + 1) * 200 + lr    ] = (c0[1] + c1[1]) + (c2[1] + c3[1]);
            gh[(b0i    ) * 200 + lr + 8] = (c0[2] + c1[2]) + (c2[2] + c3[2]);
            gh[(b0i + 1) * 200 + lr + 8] = (c0[3] + c1[3]) + (c2[3] + c3[3]);
        }
        asm volatile("cp.async.wait_group 0;" ::: "memory");
        __syncthreads();

        // ---- gates + exact-register h update + tf32 DSMEM broadcast ----
        if (t < 256) {
            float* hwr = hbuf[p ^ 1];
            const float br = bhh[j], bz = bhh[64 + j], bn = bhh[128 + j];
#pragma unroll
            for (int i = 0; i < 2; i++) {
                const int b = bb + 4 * i;
                const float hr = gh[b * 200 + j]       + br;
                const float hz = gh[b * 200 + 64 + j]  + bz;
                const float hn = gh[b * 200 + 128 + j] + bn;
                const float ir  = gi_s[b * 192 + j];
                const float iz  = gi_s[b * 192 + 64 + j];
                const float in_ = gi_s[b * 192 + 128 + j];
                const float r = __fdividef(1.0f, 1.0f + __expf(-(ir + hr)));
                const float z = __fdividef(1.0f, 1.0f + __expf(-(iz + hz)));
                const float n = tanh_fast(in_ + r * hn);
                const float hprev = (i == 0) ? hprev0 : hprev1;
                const float hnew  = (1.0f - z) * n + z * hprev;
                if (i == 0) hprev0 = hnew; else hprev1 = hnew;

                const float hop = f2tf32(hnew);        // MMA operand copy
                float* lp = hwr + kglob * HP + b;
#pragma unroll
                for (int q = 0; q < 4; q++)
                    *(float*)cluster.map_shared_rank(lp, q) = hop;

                if (store_all) {
                    hout[((size_t)ts * BATCH + B0 + b) * HID + kglob] = hnew;
                } else if (ts == T_STEPS - 1) {
                    hout[(size_t)(B0 + b) * HID + kglob] = hnew;
                }
            }
        }
        cluster.sync();
    }
}

// =============================================================================
// FC on the last hidden state
// =============================================================================
__global__ __launch_bounds__(256) void fc_kernel(
    const float* __restrict__ Wfc, const float* __restrict__ bfc,
    float* __restrict__ out)
{
    __shared__ float hs[256];
    const int b = blockIdx.x;
    const int o = threadIdx.x;
    hs[o] = g_h2[b * 256 + o];
    __syncthreads();
    const float* wr = Wfc + (size_t)o * 256;
    float acc = 0.0f;
#pragma unroll 8
    for (int k = 0; k < 256; k += 4) {
        const float4 wv = *(const float4*)(wr + k);
        acc += hs[k] * wv.x + hs[k + 1] * wv.y + hs[k + 2] * wv.z + hs[k + 3] * wv.w;
    }
    out[b * 256 + o] = acc + bfc[o];
}

// =============================================================================
extern "C" void kernel_launch(void* const* d_in, const int* in_sizes, int n_in,
                              void* d_out, int out_size)
{
    const float* x     = (const float*)d_in[0];
    const float* W_ih0 = (const float*)d_in[1];
    const float* W_hh0 = (const float*)d_in[2];
    const float* b_ih0 = (const float*)d_in[3];
    const float* b_hh0 = (const float*)d_in[4];
    const float* W_ih1 = (const float*)d_in[5];
    const float* W_hh1 = (const float*)d_in[6];
    const float* b_ih1 = (const float*)d_in[7];
    const float* b_hh1 = (const float*)d_in[8];
    const float* W_fc  = (const float*)d_in[9];
    const float* b_fc  = (const float*)d_in[10];
    float* out = (float*)d_out;

    float *gi_p, *h1_p, *h2_p;
    cudaGetSymbolAddress((void**)&gi_p, g_gi);
    cudaGetSymbolAddress((void**)&h1_p, g_h1);
    cudaGetSymbolAddress((void**)&h2_p, g_h2);

    const int M = T_STEPS * BATCH;        // 131072
    dim3 gemm_grid(G3 / 128, M / 128);    // (6, 1024)

    // layer 0: gi0 = x @ W_ih0^T + b_ih0   (tf32 HMMA, K=128)
    gemm_tf32mma<<<gemm_grid, 256>>>(x, W_ih0, b_ih0, gi_p, G3, IN0);
    // layer 0 recurrence -> g_h1[T,B,H]
    gru_rec_mma<<<128, 384>>>(W_hh0, b_hh0, gi_p, h1_p, 1);
    // layer 1: gi1 = h1 @ W_ih1^T + b_ih1  (tf32 HMMA, K=256)
    gemm_tf32mma<<<gemm_grid, 256>>>(h1_p, W_ih1, b_ih1, gi_p, G3, HID);
    // layer 1 recurrence -> g_h2[B,H]
    gru_rec_mma<<<128, 384>>>(W_hh1, b_hh1, gi_p, h2_p, 0);
    // FC head
    fc_kernel<<<BATCH, 256>>>(W_fc, b_fc, out);
}